// round 13
// baseline (speedup 1.0000x reference)
#include <cuda_runtime.h>
#include <cstdint>

#define BB_   2
#define LL_   2048
#define EE_   1024
#define HH_   16
#define DH_   64
#define FF_   4096
#define NTOK  (BB_*LL_)
#define NZ    (BB_*HH_)

// ---------------- scratch ----------------
__device__ float g_xn[NTOK*EE_];
__device__ float g_q [NTOK*EE_];
__device__ float g_k [NTOK*EE_];
__device__ float g_v [NTOK*EE_];
__device__ float g_ctx[NTOK*EE_];
__device__ float g_hidden[NTOK*EE_];
__device__ float g_hn[NTOK*EE_];
__device__ float g_up[(size_t)NTOK*FF_];
__device__ float g_S[(size_t)NZ*LL_*LL_];

// ---------------- helpers ----------------
__device__ __forceinline__ uint32_t f2tf(float x){
    uint32_t r; asm("cvt.rna.tf32.f32 %0, %1;" : "=r"(r) : "f"(x)); return r;
}
__device__ __forceinline__ void mma_tf32(float c[4], const uint32_t a[4], const uint32_t b[2]){
    asm volatile("mma.sync.aligned.m16n8k8.row.col.f32.tf32.tf32.f32 "
        "{%0,%1,%2,%3},{%4,%5,%6,%7},{%8,%9},{%0,%1,%2,%3};"
        : "+f"(c[0]), "+f"(c[1]), "+f"(c[2]), "+f"(c[3])
        : "r"(a[0]), "r"(a[1]), "r"(a[2]), "r"(a[3]), "r"(b[0]), "r"(b[1]));
}
__device__ __forceinline__ void cp16(void* dst, const void* src){
    uint32_t d = (uint32_t)__cvta_generic_to_shared(dst);
    asm volatile("cp.async.cg.shared.global [%0], [%1], 16;" :: "r"(d), "l"(src));
}
__device__ __forceinline__ void cp_commit(){ asm volatile("cp.async.commit_group;" ::: "memory"); }
template<int N> __device__ __forceinline__ void cp_wait(){
    asm volatile("cp.async.wait_group %0;" :: "n"(N) : "memory");
}

// ---------------- LayerNorm ----------------
__global__ void ln_k(const float* __restrict__ X, const float* __restrict__ w,
                     const float* __restrict__ bb, float* __restrict__ O)
{
    __shared__ float red[256];
    const int t = threadIdx.x;
    const size_t off = (size_t)blockIdx.x * EE_;
    float4 v = *(const float4*)(X + off + t*4);
    red[t] = v.x + v.y + v.z + v.w;
    __syncthreads();
    #pragma unroll
    for (int s = 128; s > 0; s >>= 1){ if (t < s) red[t] += red[t+s]; __syncthreads(); }
    float mu = red[0] * (1.f/1024.f);
    __syncthreads();
    float d0 = v.x-mu, d1 = v.y-mu, d2 = v.z-mu, d3 = v.w-mu;
    red[t] = d0*d0 + d1*d1 + d2*d2 + d3*d3;
    __syncthreads();
    #pragma unroll
    for (int s = 128; s > 0; s >>= 1){ if (t < s) red[t] += red[t+s]; __syncthreads(); }
    float inv = rsqrtf(red[0] * (1.f/1024.f) + 1e-5f);
    float4 wv = *(const float4*)(w + t*4);
    float4 bv = *(const float4*)(bb + t*4);
    float4 o;
    o.x = d0*inv*wv.x + bv.x;  o.y = d1*inv*wv.y + bv.y;
    o.z = d2*inv*wv.z + bv.z;  o.w = d3*inv*wv.w + bv.w;
    *(float4*)(O + off + t*4) = o;
}

// ---------------- tf32 GEMM, CTA tile 128x256, warp tile 64x64 ----------------
// EPI: 0 bias, 1 bias+res, 2 bias+gelu.  SPLIT: 1 = A-operand split (2 MMAs)
// smem stage: A 128x36 (4608 w), B 32x260 (8320 w) => 12928 words = 51712 B
#define GSS 12928

template<int EPI, int SPLIT>
__global__ void __launch_bounds__(256, 1) gemm_k(
    const float* __restrict__ A, const float* __restrict__ W,
    const float* __restrict__ bias, const float* __restrict__ res,
    float* __restrict__ C, int M, int N, int K)
{
    extern __shared__ float sm[];
    const int tid  = threadIdx.x;
    const int bm   = blockIdx.y*128, bn = blockIdx.x*256;
    const int lane = tid & 31, warp = tid >> 5;
    const int wm   = warp >> 2, wn = warp & 3;      // 2x4 warp grid, warp tile 64x64
    const int gid  = lane >> 2, t4 = lane & 3;

    float acc[4][8][4];
    #pragma unroll
    for (int a=0;a<4;a++)
    #pragma unroll
    for (int b=0;b<8;b++)
    #pragma unroll
    for (int c=0;c<4;c++) acc[a][b][c] = 0.f;

    const int ar = tid >> 3, ac4 = tid & 7;    // A: 4 float4/thread, rows ar+32i
    const int br = tid >> 3, bc  = tid & 7;    // B: 8 float4/thread, row br, cols bc+8i
    const float* Ap = A + (size_t)(bm+ar)*K + ac4*4;
    const float* Wp = W + (size_t)br*N + bn + bc*4;
    const int KT = K >> 5;

    auto issue = [&](int t){
        float* As = sm + (t&1)*GSS;
        float* Bs = As + 4608;
        const float* ap = Ap + t*32;
        const float* wp = Wp + (size_t)t*32*N;
        #pragma unroll
        for (int i=0;i<4;i++) cp16(As + (ar+32*i)*36 + ac4*4, ap + (size_t)(32*i)*K);
        #pragma unroll
        for (int i=0;i<8;i++) cp16(Bs + br*260 + (bc+8*i)*4, wp + 32*i);
        cp_commit();
    };

    issue(0);
    for (int t = 0; t < KT; t++){
        if (t+1 < KT){ issue(t+1); cp_wait<1>(); }
        else         { cp_wait<0>(); }
        __syncthreads();
        const float* As = sm + (t&1)*GSS;
        const float* Bs = As + 4608;
        #pragma unroll
        for (int ks=0;ks<4;ks++){
            uint32_t ah[4][4], al[4][4], bh[8][2];
            #pragma unroll
            for (int mi=0;mi<4;mi++){
                const int r0 = (wm*64 + mi*16 + gid)*36 + ks*8 + t4;
                float x0 = As[r0], x1 = As[r0+8*36], x2 = As[r0+4], x3 = As[r0+8*36+4];
                ah[mi][0]=f2tf(x0); ah[mi][1]=f2tf(x1); ah[mi][2]=f2tf(x2); ah[mi][3]=f2tf(x3);
                if (SPLIT){
                    al[mi][0]=f2tf(x0-__uint_as_float(ah[mi][0]));
                    al[mi][1]=f2tf(x1-__uint_as_float(ah[mi][1]));
                    al[mi][2]=f2tf(x2-__uint_as_float(ah[mi][2]));
                    al[mi][3]=f2tf(x3-__uint_as_float(ah[mi][3]));
                }
            }
            #pragma unroll
            for (int ni=0;ni<8;ni++){
                const int c0 = wn*64 + ni*8 + gid;
                bh[ni][0]=f2tf(Bs[(ks*8+t4)*260 + c0]);
                bh[ni][1]=f2tf(Bs[(ks*8+t4+4)*260 + c0]);
            }
            #pragma unroll
            for (int mi=0;mi<4;mi++)
            #pragma unroll
            for (int ni=0;ni<8;ni++){
                mma_tf32(acc[mi][ni], ah[mi], bh[ni]);
                if (SPLIT) mma_tf32(acc[mi][ni], al[mi], bh[ni]);
            }
        }
        __syncthreads();
    }

    #pragma unroll
    for (int mi=0;mi<4;mi++)
    #pragma unroll
    for (int ni=0;ni<8;ni++){
        const int row0 = bm + wm*64 + mi*16 + gid;
        const int col0 = bn + wn*64 + ni*8 + t4*2;
        #pragma unroll
        for (int i=0;i<4;i++){
            const int row = row0 + ((i>=2)?8:0);
            const int col = col0 + (i&1);
            float v = acc[mi][ni][i] + bias[col];
            if (EPI == 1) v += res[(size_t)row*N + col];
            if (EPI == 2) v = 0.5f*v*(1.0f + erff(v*0.70710678118654752f));
            C[(size_t)row*N + col] = v;
        }
    }
}

// ---------------- attention scores: S[z,l,m] = 8 * q.k  (full 3-MMA split) ----------------
__global__ void __launch_bounds__(256) attn_score_k(
    const float* __restrict__ Q, const float* __restrict__ Kx, float* __restrict__ S)
{
    __shared__ float Qs[128*36];
    __shared__ float Ks[128*36];
    const int tid  = threadIdx.x;
    const int z = blockIdx.z, b = z >> 4, h = z & 15;
    const int bm = blockIdx.y*128, bn = blockIdx.x*128;
    const int lane = tid & 31, warp = tid >> 5;
    const int wm = warp >> 2, wn = warp & 3;
    const int gid = lane >> 2, t4 = lane & 3;

    float acc[4][4][4];
    #pragma unroll
    for (int a=0;a<4;a++)
    #pragma unroll
    for (int c=0;c<4;c++)
    #pragma unroll
    for (int i=0;i<4;i++) acc[a][c][i] = 0.f;

    const int ar = tid >> 3, ac4 = tid & 7;
    const float* Qp = Q  + ((size_t)(b*LL_ + bm + ar)*HH_ + h)*DH_ + ac4*4;
    const float* Kp = Kx + ((size_t)(b*LL_ + bn + ar)*HH_ + h)*DH_ + ac4*4;

    #pragma unroll
    for (int kt = 0; kt < 2; kt++){
        float4 qr[4], kr[4];
        #pragma unroll
        for (int i=0;i<4;i++){
            qr[i] = *(const float4*)(Qp + kt*32 + (size_t)(32*i)*1024);
            kr[i] = *(const float4*)(Kp + kt*32 + (size_t)(32*i)*1024);
        }
        if (kt) __syncthreads();
        #pragma unroll
        for (int i=0;i<4;i++){
            *(float4*)(Qs + (ar+32*i)*36 + ac4*4) = qr[i];
            *(float4*)(Ks + (ar+32*i)*36 + ac4*4) = kr[i];
        }
        __syncthreads();
        #pragma unroll
        for (int ks=0;ks<4;ks++){
            uint32_t ah[4][4], al[4][4], bh[4][2], bl[4][2];
            #pragma unroll
            for (int mi=0;mi<4;mi++){
                const int r0 = (wm*64 + mi*16 + gid)*36 + ks*8 + t4;
                float x0 = Qs[r0], x1 = Qs[r0+8*36], x2 = Qs[r0+4], x3 = Qs[r0+8*36+4];
                ah[mi][0]=f2tf(x0); ah[mi][1]=f2tf(x1); ah[mi][2]=f2tf(x2); ah[mi][3]=f2tf(x3);
                al[mi][0]=f2tf(x0-__uint_as_float(ah[mi][0]));
                al[mi][1]=f2tf(x1-__uint_as_float(ah[mi][1]));
                al[mi][2]=f2tf(x2-__uint_as_float(ah[mi][2]));
                al[mi][3]=f2tf(x3-__uint_as_float(ah[mi][3]));
            }
            #pragma unroll
            for (int ni=0;ni<4;ni++){
                const int c0 = wn*32 + ni*8 + gid;
                float y0 = Ks[c0*36 + ks*8 + t4];
                float y1 = Ks[c0*36 + ks*8 + t4 + 4];
                bh[ni][0]=f2tf(y0); bh[ni][1]=f2tf(y1);
                bl[ni][0]=f2tf(y0-__uint_as_float(bh[ni][0]));
                bl[ni][1]=f2tf(y1-__uint_as_float(bh[ni][1]));
            }
            #pragma unroll
            for (int mi=0;mi<4;mi++)
            #pragma unroll
            for (int ni=0;ni<4;ni++){
                mma_tf32(acc[mi][ni], ah[mi], bh[ni]);
                mma_tf32(acc[mi][ni], ah[mi], bl[ni]);
                mma_tf32(acc[mi][ni], al[mi], bh[ni]);
            }
        }
    }

    float* Sz = S + (size_t)z*LL_*LL_;
    #pragma unroll
    for (int mi=0;mi<4;mi++)
    #pragma unroll
    for (int ni=0;ni<4;ni++){
        const int row0 = bm + wm*64 + mi*16 + gid;
        const int col0 = bn + wn*32 + ni*8 + t4*2;
        #pragma unroll
        for (int i=0;i<4;i++){
            const int row = row0 + ((i>=2)?8:0);
            const int col = col0 + (i&1);
            Sz[(size_t)row*LL_ + col] = 8.0f * acc[mi][ni][i];
        }
    }
}

// ---------------- row softmax (warp-shuffle reductions) ----------------
__global__ void softmax_k(float* __restrict__ S)
{
    __shared__ float redm[8];
    __shared__ float reds[8];
    const int t = threadIdx.x, lane = t & 31, w = t >> 5;
    float4* row = (float4*)(S + (size_t)blockIdx.y*LL_*LL_ + (size_t)blockIdx.x*LL_);
    float4 v0 = row[t], v1 = row[t+256];
    float m = fmaxf(fmaxf(fmaxf(v0.x,v0.y), fmaxf(v0.z,v0.w)),
                    fmaxf(fmaxf(v1.x,v1.y), fmaxf(v1.z,v1.w)));
    #pragma unroll
    for (int o=16;o>0;o>>=1) m = fmaxf(m, __shfl_xor_sync(0xFFFFFFFFu, m, o));
    if (lane == 0) redm[w] = m;
    __syncthreads();
    m = redm[0];
    #pragma unroll
    for (int i=1;i<8;i++) m = fmaxf(m, redm[i]);
    v0.x = expf(v0.x-m); v0.y = expf(v0.y-m); v0.z = expf(v0.z-m); v0.w = expf(v0.w-m);
    v1.x = expf(v1.x-m); v1.y = expf(v1.y-m); v1.z = expf(v1.z-m); v1.w = expf(v1.w-m);
    float s = v0.x+v0.y+v0.z+v0.w + v1.x+v1.y+v1.z+v1.w;
    #pragma unroll
    for (int o=16;o>0;o>>=1) s += __shfl_xor_sync(0xFFFFFFFFu, s, o);
    if (lane == 0) reds[w] = s;
    __syncthreads();
    s = reds[0];
    #pragma unroll
    for (int i=1;i<8;i++) s += reds[i];
    const float inv = 1.0f / s;
    v0.x*=inv; v0.y*=inv; v0.z*=inv; v0.w*=inv;
    v1.x*=inv; v1.y*=inv; v1.z*=inv; v1.w*=inv;
    row[t] = v0; row[t+256] = v1;
}

// ---------------- ctx = P @ V ----------------
#define VSS 6912

__global__ void __launch_bounds__(256, 2) attn_av_k(
    const float* __restrict__ P, const float* __restrict__ V, float* __restrict__ Ctx)
{
    extern __shared__ float sm[];
    const int tid  = threadIdx.x;
    const int z = blockIdx.y, b = z >> 4, h = z & 15;
    const int bm = blockIdx.x*128;
    const int lane = tid & 31, warp = tid >> 5;
    const int wm = warp >> 1, wn = warp & 1;
    const int gid = lane >> 2, t4 = lane & 3;

    float acc[2][4][4];
    #pragma unroll
    for (int a=0;a<2;a++)
    #pragma unroll
    for (int c=0;c<4;c++)
    #pragma unroll
    for (int i=0;i<4;i++) acc[a][c][i] = 0.f;

    const int ar = tid >> 3, ac4 = tid & 7;
    const int vr = tid >> 4, vc4 = tid & 15;
    const float* Pp = P + (size_t)z*LL_*LL_ + (size_t)(bm+ar)*LL_ + ac4*4;
    const float* Vp = V + ((size_t)(b*LL_ + vr)*HH_ + h)*DH_ + vc4*4;
    const int KT = LL_/32;

    auto issue = [&](int t){
        float* Ps = sm + (t&1)*VSS;
        float* Vs = Ps + 4608;
        const int k0 = t*32;
        #pragma unroll
        for (int i=0;i<4;i++) cp16(Ps + (ar+32*i)*36 + ac4*4, Pp + k0 + (size_t)(32*i)*LL_);
        #pragma unroll
        for (int i=0;i<2;i++) cp16(Vs + (vr+16*i)*72 + vc4*4, Vp + (size_t)(k0+16*i)*1024);
        cp_commit();
    };

    issue(0);
    for (int t = 0; t < KT; t++){
        if (t+1 < KT){ issue(t+1); cp_wait<1>(); }
        else         { cp_wait<0>(); }
        __syncthreads();
        const float* Ps = sm + (t&1)*VSS;
        const float* Vs = Ps + 4608;
        #pragma unroll
        for (int ks=0;ks<4;ks++){
            uint32_t a[2][4], bfr[4][2];
            #pragma unroll
            for (int mi=0;mi<2;mi++){
                const int r0 = (wm*32 + mi*16 + gid)*36 + ks*8 + t4;
                a[mi][0]=f2tf(Ps[r0]);     a[mi][1]=f2tf(Ps[r0+8*36]);
                a[mi][2]=f2tf(Ps[r0+4]);   a[mi][3]=f2tf(Ps[r0+8*36+4]);
            }
            #pragma unroll
            for (int ni=0;ni<4;ni++){
                const int c0 = wn*32 + ni*8 + gid;
                bfr[ni][0] = f2tf(Vs[(ks*8+t4)*72 + c0]);
                bfr[ni][1] = f2tf(Vs[(ks*8+t4+4)*72 + c0]);
            }
            #pragma unroll
            for (int mi=0;mi<2;mi++)
            #pragma unroll
            for (int ni=0;ni<4;ni++)
                mma_tf32(acc[mi][ni], a[mi], bfr[ni]);
        }
        __syncthreads();
    }

    #pragma unroll
    for (int mi=0;mi<2;mi++)
    #pragma unroll
    for (int ni=0;ni<4;ni++){
        const int row0 = bm + wm*32 + mi*16 + gid;
        const int col0 = wn*32 + ni*8 + t4*2;
        #pragma unroll
        for (int i=0;i<4;i++){
            const int row = row0 + ((i>=2)?8:0);
            const int col = col0 + (i&1);
            Ctx[((size_t)(b*LL_ + row)*HH_ + h)*DH_ + col] = acc[mi][ni][i];
        }
    }
}

// ---------------- launch ----------------
extern "C" void kernel_launch(void* const* d_in, const int* in_sizes, int n_in,
                              void* d_out, int out_size)
{
    const float* x     = (const float*)d_in[0];
    const float* ln1_w = (const float*)d_in[1];
    const float* ln1_b = (const float*)d_in[2];
    const float* wq    = (const float*)d_in[3];
    const float* bq    = (const float*)d_in[4];
    const float* wk    = (const float*)d_in[5];
    const float* bk    = (const float*)d_in[6];
    const float* wv    = (const float*)d_in[7];
    const float* bv    = (const float*)d_in[8];
    const float* wo    = (const float*)d_in[9];
    const float* bo    = (const float*)d_in[10];
    const float* ln2_w = (const float*)d_in[11];
    const float* ln2_b = (const float*)d_in[12];
    const float* wu    = (const float*)d_in[13];
    const float* bu    = (const float*)d_in[14];
    const float* wd    = (const float*)d_in[15];
    const float* bd    = (const float*)d_in[16];
    float* out = (float*)d_out;

    float *xn,*q,*k,*v,*ctx,*hidden,*hn,*up,*S;
    cudaGetSymbolAddress((void**)&xn,  g_xn);
    cudaGetSymbolAddress((void**)&q,   g_q);
    cudaGetSymbolAddress((void**)&k,   g_k);
    cudaGetSymbolAddress((void**)&v,   g_v);
    cudaGetSymbolAddress((void**)&ctx, g_ctx);
    cudaGetSymbolAddress((void**)&hidden, g_hidden);
    cudaGetSymbolAddress((void**)&hn,  g_hn);
    cudaGetSymbolAddress((void**)&up,  g_up);
    cudaGetSymbolAddress((void**)&S,   g_S);

    const int SMG = 2*GSS*4;   // 103424
    const int SMV = 2*VSS*4;   // 55296
    cudaFuncSetAttribute(gemm_k<0,1>, cudaFuncAttributeMaxDynamicSharedMemorySize, SMG);
    cudaFuncSetAttribute(gemm_k<0,0>, cudaFuncAttributeMaxDynamicSharedMemorySize, SMG);
    cudaFuncSetAttribute(gemm_k<1,0>, cudaFuncAttributeMaxDynamicSharedMemorySize, SMG);
    cudaFuncSetAttribute(gemm_k<2,0>, cudaFuncAttributeMaxDynamicSharedMemorySize, SMG);
    cudaFuncSetAttribute(attn_av_k,   cudaFuncAttributeMaxDynamicSharedMemorySize, SMV);

    const dim3 blk(256);
    const dim3 gE(EE_/256, NTOK/128);    // (4, 32)
    const dim3 gF(FF_/256, NTOK/128);    // (16, 32)

    // 1. LN1
    ln_k<<<NTOK, blk>>>(x, ln1_w, ln1_b, xn);
    // 2. Q, K (A-split 2-MMA), V (single)
    gemm_k<0,1><<<gE, blk, SMG>>>(xn, wq, bq, nullptr, q, NTOK, EE_, EE_);
    gemm_k<0,1><<<gE, blk, SMG>>>(xn, wk, bk, nullptr, k, NTOK, EE_, EE_);
    gemm_k<0,0><<<gE, blk, SMG>>>(xn, wv, bv, nullptr, v, NTOK, EE_, EE_);
    // 3. scores (full split), softmax (shuffle), context
    attn_score_k<<<dim3(LL_/128, LL_/128, NZ), blk>>>(q, k, S);
    softmax_k   <<<dim3(LL_, NZ), blk>>>(S);
    attn_av_k   <<<dim3(LL_/128, NZ), blk, SMV>>>(S, v, ctx);
    // 4. O proj + residual
    gemm_k<1,0><<<gE, blk, SMG>>>(ctx, wo, bo, x, hidden, NTOK, EE_, EE_);
    // 5. LN2 + FFN
    ln_k<<<NTOK, blk>>>(hidden, ln2_w, ln2_b, hn);
    gemm_k<2,0><<<gF, blk, SMG>>>(hn, wu, bu, nullptr, up, NTOK, FF_, EE_);
    gemm_k<1,0><<<gE, blk, SMG>>>(up, wd, bd, hidden, out, NTOK, EE_, FF_);
    (void)in_sizes; (void)n_in; (void)out_size;
}

// round 15
// speedup vs baseline: 1.0020x; 1.0020x over previous
#include <cuda_runtime.h>
#include <cstdint>

#define BB_   2
#define LL_   2048
#define EE_   1024
#define HH_   16
#define DH_   64
#define FF_   4096
#define NTOK  (BB_*LL_)
#define NZ    (BB_*HH_)

// ---------------- scratch ----------------
__device__ float g_xn[NTOK*EE_];
__device__ float g_q [NTOK*EE_];
__device__ float g_k [NTOK*EE_];
__device__ float g_v [NTOK*EE_];
__device__ float g_ctx[NTOK*EE_];
__device__ float g_hidden[NTOK*EE_];
__device__ float g_hn[NTOK*EE_];
__device__ float g_up[(size_t)NTOK*FF_];

// ---------------- helpers ----------------
__device__ __forceinline__ uint32_t f2tf(float x){
    uint32_t r; asm("cvt.rna.tf32.f32 %0, %1;" : "=r"(r) : "f"(x)); return r;
}
__device__ __forceinline__ void mma_tf32(float c[4], const uint32_t a[4], const uint32_t b[2]){
    asm volatile("mma.sync.aligned.m16n8k8.row.col.f32.tf32.tf32.f32 "
        "{%0,%1,%2,%3},{%4,%5,%6,%7},{%8,%9},{%0,%1,%2,%3};"
        : "+f"(c[0]), "+f"(c[1]), "+f"(c[2]), "+f"(c[3])
        : "r"(a[0]), "r"(a[1]), "r"(a[2]), "r"(a[3]), "r"(b[0]), "r"(b[1]));
}
__device__ __forceinline__ void cp16(void* dst, const void* src){
    uint32_t d = (uint32_t)__cvta_generic_to_shared(dst);
    asm volatile("cp.async.cg.shared.global [%0], [%1], 16;" :: "r"(d), "l"(src));
}
__device__ __forceinline__ void cp_commit(){ asm volatile("cp.async.commit_group;" ::: "memory"); }
template<int N> __device__ __forceinline__ void cp_wait(){
    asm volatile("cp.async.wait_group %0;" :: "n"(N) : "memory");
}

// ---------------- LayerNorm ----------------
__global__ void ln_k(const float* __restrict__ X, const float* __restrict__ w,
                     const float* __restrict__ bb, float* __restrict__ O)
{
    __shared__ float red[256];
    const int t = threadIdx.x;
    const size_t off = (size_t)blockIdx.x * EE_;
    float4 v = *(const float4*)(X + off + t*4);
    red[t] = v.x + v.y + v.z + v.w;
    __syncthreads();
    #pragma unroll
    for (int s = 128; s > 0; s >>= 1){ if (t < s) red[t] += red[t+s]; __syncthreads(); }
    float mu = red[0] * (1.f/1024.f);
    __syncthreads();
    float d0 = v.x-mu, d1 = v.y-mu, d2 = v.z-mu, d3 = v.w-mu;
    red[t] = d0*d0 + d1*d1 + d2*d2 + d3*d3;
    __syncthreads();
    #pragma unroll
    for (int s = 128; s > 0; s >>= 1){ if (t < s) red[t] += red[t+s]; __syncthreads(); }
    float inv = rsqrtf(red[0] * (1.f/1024.f) + 1e-5f);
    float4 wv = *(const float4*)(w + t*4);
    float4 bv = *(const float4*)(bb + t*4);
    float4 o;
    o.x = d0*inv*wv.x + bv.x;  o.y = d1*inv*wv.y + bv.y;
    o.z = d2*inv*wv.z + bv.z;  o.w = d3*inv*wv.w + bv.w;
    *(float4*)(O + off + t*4) = o;
}

// ---------------- tf32 GEMM (R12 config): CTA 128x128, warp 64x32 ----------------
// EPI: 0 bias, 1 bias+res, 2 bias+gelu.  SPLIT: 1 = A-operand split (2 MMAs)
#define GSS 8832   // 128*36 + 32*132

template<int EPI, int SPLIT, int MINB>
__global__ void __launch_bounds__(256, MINB) gemm_k(
    const float* __restrict__ A, const float* __restrict__ W,
    const float* __restrict__ bias, const float* __restrict__ res,
    float* __restrict__ C, int M, int N, int K)
{
    extern __shared__ float sm[];
    const int tid  = threadIdx.x;
    const int bm   = blockIdx.y*128, bn = blockIdx.x*128;
    const int lane = tid & 31, warp = tid >> 5;
    const int wm   = warp >> 2, wn = warp & 3;
    const int gid  = lane >> 2, t4 = lane & 3;

    float acc[4][4][4];
    #pragma unroll
    for (int a=0;a<4;a++)
    #pragma unroll
    for (int b=0;b<4;b++)
    #pragma unroll
    for (int c=0;c<4;c++) acc[a][b][c] = 0.f;

    const int ar = tid >> 3, ac4 = tid & 7;
    const int br = tid >> 5, bc4 = tid & 31;
    const float* Ap = A + (size_t)(bm+ar)*K + ac4*4;
    const float* Wp = W + (size_t)br*N + bn + bc4*4;
    const int KT = K >> 5;

    auto issue = [&](int t){
        float* As = sm + (t&1)*GSS;
        float* Bs = As + 4608;
        const float* ap = Ap + t*32;
        const float* wp = Wp + (size_t)t*32*N;
        #pragma unroll
        for (int i=0;i<4;i++) cp16(As + (ar+32*i)*36 + ac4*4, ap + (size_t)(32*i)*K);
        #pragma unroll
        for (int i=0;i<4;i++) cp16(Bs + (br+8*i)*132 + bc4*4, wp + (size_t)(8*i)*N);
        cp_commit();
    };

    issue(0);
    for (int t = 0; t < KT; t++){
        if (t+1 < KT){ issue(t+1); cp_wait<1>(); }
        else         { cp_wait<0>(); }
        __syncthreads();
        const float* As = sm + (t&1)*GSS;
        const float* Bs = As + 4608;
        #pragma unroll
        for (int ks=0;ks<4;ks++){
            uint32_t ah[4][4], al[4][4], bh[4][2];
            #pragma unroll
            for (int mi=0;mi<4;mi++){
                const int r0 = (wm*64 + mi*16 + gid)*36 + ks*8 + t4;
                float x0 = As[r0], x1 = As[r0+8*36], x2 = As[r0+4], x3 = As[r0+8*36+4];
                ah[mi][0]=f2tf(x0); ah[mi][1]=f2tf(x1); ah[mi][2]=f2tf(x2); ah[mi][3]=f2tf(x3);
                if (SPLIT){
                    al[mi][0]=f2tf(x0-__uint_as_float(ah[mi][0]));
                    al[mi][1]=f2tf(x1-__uint_as_float(ah[mi][1]));
                    al[mi][2]=f2tf(x2-__uint_as_float(ah[mi][2]));
                    al[mi][3]=f2tf(x3-__uint_as_float(ah[mi][3]));
                }
            }
            #pragma unroll
            for (int ni=0;ni<4;ni++){
                const int c0 = wn*32 + ni*8 + gid;
                bh[ni][0]=f2tf(Bs[(ks*8+t4)*132 + c0]);
                bh[ni][1]=f2tf(Bs[(ks*8+t4+4)*132 + c0]);
            }
            #pragma unroll
            for (int mi=0;mi<4;mi++)
            #pragma unroll
            for (int ni=0;ni<4;ni++){
                mma_tf32(acc[mi][ni], ah[mi], bh[ni]);
                if (SPLIT) mma_tf32(acc[mi][ni], al[mi], bh[ni]);
            }
        }
        __syncthreads();
    }

    #pragma unroll
    for (int mi=0;mi<4;mi++)
    #pragma unroll
    for (int ni=0;ni<4;ni++){
        const int row0 = bm + wm*64 + mi*16 + gid;
        const int col0 = bn + wn*32 + ni*8 + t4*2;
        #pragma unroll
        for (int i=0;i<4;i++){
            const int row = row0 + ((i>=2)?8:0);
            const int col = col0 + (i&1);
            float v = acc[mi][ni][i] + bias[col];
            if (EPI == 1) v += res[(size_t)row*N + col];
            if (EPI == 2) v = 0.5f*v*(1.0f + erff(v*0.70710678118654752f));
            C[(size_t)row*N + col] = v;
        }
    }
}

// ---------------- flash attention: ctx = softmax(8*QK^T) @ V ----------------
// grid (LL/128, NZ), 8 warps; warp owns 16 q rows x all keys. Key tile = 64.
// smem (floats): Qs 2 chunks x 128x36 (d 0..31 | 32..63)      @ 0     (9216)
//                2 stages x [Ks 2 x 64x36 | Vs 64x72]          @ 9216  (2x9216)
//                Ps 128x68                                     @ 27648 (8704)
#define FQ    9216
#define FSTG  9216
#define FPS   27648
#define FSMEM ((FPS + 8704)*4)   // 145408 B

__global__ void __launch_bounds__(256, 1) flash_k(
    const float* __restrict__ Q, const float* __restrict__ K,
    const float* __restrict__ V, float* __restrict__ Ctx)
{
    extern __shared__ float sm[];
    const int tid = threadIdx.x, warp = tid >> 5, lane = tid & 31;
    const int gid = lane >> 2, t4 = lane & 3;
    const int z = blockIdx.y, b = z >> 4, h = z & 15;
    const int bm = blockIdx.x*128;
    float* Qs = sm;
    float* Ps = sm + FPS;

    // ---- Q tile: 128 rows x 64 d, two 36-stride chunks ----
    {
        const int crow = tid >> 1, half = tid & 1;
        const float* qp = Q + ((size_t)(b*LL_ + bm + crow)*HH_ + h)*DH_ + half*32;
        #pragma unroll
        for (int i=0;i<8;i++) cp16(Qs + half*4608 + crow*36 + i*4, qp + i*4);
    }
    // ---- KV tile loader: 64 keys x 64 d ----
    const int krow = tid >> 2, kq = tid & 3;
    auto issueKV = [&](int j){
        float* Ks = sm + FQ + (j&1)*FSTG;       // 2 chunks of 64x36
        float* Vs = Ks + 4608;                   // 64x72
        const float* kp = K + ((size_t)(b*LL_ + j*64 + krow)*HH_ + h)*DH_;
        const float* vp = V + ((size_t)(b*LL_ + j*64 + krow)*HH_ + h)*DH_;
        #pragma unroll
        for (int i=0;i<4;i++){
            const int d = kq*16 + i*4;
            const int chunk = d >> 5, col = d & 31;
            cp16(Ks + chunk*2304 + krow*36 + col, kp + d);
            cp16(Vs + krow*72 + d, vp + d);
        }
        cp_commit();
    };
    issueKV(0);

    float m_s[2] = {-1e30f, -1e30f};
    float l_s[2] = {0.f, 0.f};
    float acc_o[8][4];
    #pragma unroll
    for (int n=0;n<8;n++)
    #pragma unroll
    for (int i=0;i<4;i++) acc_o[n][i] = 0.f;

    const int NT = LL_/64;   // 32
    for (int j = 0; j < NT; j++){
        if (j+1 < NT){ issueKV(j+1); cp_wait<1>(); }
        else         { cp_wait<0>(); }
        __syncthreads();
        const float* Ks = sm + FQ + (j&1)*FSTG;
        const float* Vs = Ks + 4608;

        // ---- S tile 16x64 per warp: 3-MMA split over 8 k-slices ----
        float s_acc[8][4];
        #pragma unroll
        for (int n=0;n<8;n++)
        #pragma unroll
        for (int i=0;i<4;i++) s_acc[n][i] = 0.f;
        #pragma unroll
        for (int kt=0;kt<2;kt++)
        #pragma unroll
        for (int ks=0;ks<4;ks++){
            uint32_t ah[4], al[4];
            const int r0 = kt*4608 + (warp*16 + gid)*36 + ks*8 + t4;
            float x0 = Qs[r0], x1 = Qs[r0+8*36], x2 = Qs[r0+4], x3 = Qs[r0+8*36+4];
            ah[0]=f2tf(x0); ah[1]=f2tf(x1); ah[2]=f2tf(x2); ah[3]=f2tf(x3);
            al[0]=f2tf(x0-__uint_as_float(ah[0]));
            al[1]=f2tf(x1-__uint_as_float(ah[1]));
            al[2]=f2tf(x2-__uint_as_float(ah[2]));
            al[3]=f2tf(x3-__uint_as_float(ah[3]));
            #pragma unroll
            for (int ni=0;ni<8;ni++){
                const int c = kt*2304 + (ni*8 + gid)*36 + ks*8 + t4;
                float y0 = Ks[c], y1 = Ks[c+4];
                uint32_t bh[2] = { f2tf(y0), f2tf(y1) };
                uint32_t bl[2] = { f2tf(y0-__uint_as_float(bh[0])),
                                   f2tf(y1-__uint_as_float(bh[1])) };
                mma_tf32(s_acc[ni], ah, bh);
                mma_tf32(s_acc[ni], ah, bl);
                mma_tf32(s_acc[ni], al, bh);
            }
        }
        // ---- online softmax (rows warp*16+gid, +8; reduction over t4 lanes) ----
        float mx0 = -1e30f, mx1 = -1e30f;
        #pragma unroll
        for (int ni=0;ni<8;ni++){
            s_acc[ni][0]*=8.f; s_acc[ni][1]*=8.f; s_acc[ni][2]*=8.f; s_acc[ni][3]*=8.f;
            mx0 = fmaxf(mx0, fmaxf(s_acc[ni][0], s_acc[ni][1]));
            mx1 = fmaxf(mx1, fmaxf(s_acc[ni][2], s_acc[ni][3]));
        }
        mx0 = fmaxf(mx0, __shfl_xor_sync(0xFFFFFFFFu, mx0, 1));
        mx0 = fmaxf(mx0, __shfl_xor_sync(0xFFFFFFFFu, mx0, 2));
        mx1 = fmaxf(mx1, __shfl_xor_sync(0xFFFFFFFFu, mx1, 1));
        mx1 = fmaxf(mx1, __shfl_xor_sync(0xFFFFFFFFu, mx1, 2));
        const float mn0 = fmaxf(m_s[0], mx0), mn1 = fmaxf(m_s[1], mx1);
        const float a0 = expf(m_s[0]-mn0),  a1 = expf(m_s[1]-mn1);
        float sum0 = 0.f, sum1 = 0.f;
        #pragma unroll
        for (int ni=0;ni<8;ni++){
            float p0 = expf(s_acc[ni][0]-mn0), p1 = expf(s_acc[ni][1]-mn0);
            float p2 = expf(s_acc[ni][2]-mn1), p3 = expf(s_acc[ni][3]-mn1);
            sum0 += p0+p1; sum1 += p2+p3;
            const int cb = ni*8 + 2*t4;
            float2 v01 = {p0,p1}, v23 = {p2,p3};
            *(float2*)(Ps + (warp*16+gid)*68 + cb)   = v01;
            *(float2*)(Ps + (warp*16+gid+8)*68 + cb) = v23;
        }
        sum0 += __shfl_xor_sync(0xFFFFFFFFu, sum0, 1);
        sum0 += __shfl_xor_sync(0xFFFFFFFFu, sum0, 2);
        sum1 += __shfl_xor_sync(0xFFFFFFFFu, sum1, 1);
        sum1 += __shfl_xor_sync(0xFFFFFFFFu, sum1, 2);
        l_s[0] = l_s[0]*a0 + sum0;  l_s[1] = l_s[1]*a1 + sum1;
        m_s[0] = mn0;               m_s[1] = mn1;
        #pragma unroll
        for (int ni=0;ni<8;ni++){
            acc_o[ni][0]*=a0; acc_o[ni][1]*=a0; acc_o[ni][2]*=a1; acc_o[ni][3]*=a1;
        }
        __syncwarp();   // P is warp-local: own rows written, own rows read
        // ---- O += P @ V  (8 k-slices over 64 keys) ----
        #pragma unroll
        for (int k8=0;k8<8;k8++){
            uint32_t a[4];
            const int r = (warp*16 + gid)*68 + k8*8 + t4;
            a[0]=f2tf(Ps[r]);   a[1]=f2tf(Ps[r+8*68]);
            a[2]=f2tf(Ps[r+4]); a[3]=f2tf(Ps[r+8*68+4]);
            #pragma unroll
            for (int ni=0;ni<8;ni++){
                uint32_t bb[2];
                bb[0] = f2tf(Vs[(k8*8+t4)*72 + ni*8 + gid]);
                bb[1] = f2tf(Vs[(k8*8+t4+4)*72 + ni*8 + gid]);
                mma_tf32(acc_o[ni], a, bb);
            }
        }
        __syncthreads();   // protect KV buffer reuse next iteration
    }

    // ---- epilogue ----
    const float inv0 = 1.f/l_s[0], inv1 = 1.f/l_s[1];
    const int r0 = bm + warp*16 + gid, r1 = r0 + 8;
    float* c0p = Ctx + ((size_t)(b*LL_ + r0)*HH_ + h)*DH_;
    float* c1p = Ctx + ((size_t)(b*LL_ + r1)*HH_ + h)*DH_;
    #pragma unroll
    for (int ni=0;ni<8;ni++){
        const int cb = ni*8 + 2*t4;
        float2 o0 = { acc_o[ni][0]*inv0, acc_o[ni][1]*inv0 };
        float2 o1 = { acc_o[ni][2]*inv1, acc_o[ni][3]*inv1 };
        *(float2*)(c0p + cb) = o0;
        *(float2*)(c1p + cb) = o1;
    }
}

// ---------------- launch ----------------
extern "C" void kernel_launch(void* const* d_in, const int* in_sizes, int n_in,
                              void* d_out, int out_size)
{
    const float* x     = (const float*)d_in[0];
    const float* ln1_w = (const float*)d_in[1];
    const float* ln1_b = (const float*)d_in[2];
    const float* wq    = (const float*)d_in[3];
    const float* bq    = (const float*)d_in[4];
    const float* wk    = (const float*)d_in[5];
    const float* bk    = (const float*)d_in[6];
    const float* wv    = (const float*)d_in[7];
    const float* bv    = (const float*)d_in[8];
    const float* wo    = (const float*)d_in[9];
    const float* bo    = (const float*)d_in[10];
    const float* ln2_w = (const float*)d_in[11];
    const float* ln2_b = (const float*)d_in[12];
    const float* wu    = (const float*)d_in[13];
    const float* bu    = (const float*)d_in[14];
    const float* wd    = (const float*)d_in[15];
    const float* bd    = (const float*)d_in[16];
    float* out = (float*)d_out;

    float *xn,*q,*k,*v,*ctx,*hidden,*hn,*up;
    cudaGetSymbolAddress((void**)&xn,  g_xn);
    cudaGetSymbolAddress((void**)&q,   g_q);
    cudaGetSymbolAddress((void**)&k,   g_k);
    cudaGetSymbolAddress((void**)&v,   g_v);
    cudaGetSymbolAddress((void**)&ctx, g_ctx);
    cudaGetSymbolAddress((void**)&hidden, g_hidden);
    cudaGetSymbolAddress((void**)&hn,  g_hn);
    cudaGetSymbolAddress((void**)&up,  g_up);

    const int SMG = 2*GSS*4;   // 70656
    cudaFuncSetAttribute(gemm_k<0,1,1>, cudaFuncAttributeMaxDynamicSharedMemorySize, SMG);
    cudaFuncSetAttribute(gemm_k<0,0,2>, cudaFuncAttributeMaxDynamicSharedMemorySize, SMG);
    cudaFuncSetAttribute(gemm_k<1,0,2>, cudaFuncAttributeMaxDynamicSharedMemorySize, SMG);
    cudaFuncSetAttribute(gemm_k<2,0,2>, cudaFuncAttributeMaxDynamicSharedMemorySize, SMG);
    cudaFuncSetAttribute(flash_k,       cudaFuncAttributeMaxDynamicSharedMemorySize, FSMEM);

    const dim3 blk(256);
    const dim3 gE(EE_/128, NTOK/128);    // (8, 32)
    const dim3 gF(FF_/128, NTOK/128);    // (32, 32)

    // 1. LN1
    ln_k<<<NTOK, blk>>>(x, ln1_w, ln1_b, xn);
    // 2. Q, K (A-split 2-MMA), V (single)
    gemm_k<0,1,1><<<gE, blk, SMG>>>(xn, wq, bq, nullptr, q, NTOK, EE_, EE_);
    gemm_k<0,1,1><<<gE, blk, SMG>>>(xn, wk, bk, nullptr, k, NTOK, EE_, EE_);
    gemm_k<0,0,2><<<gE, blk, SMG>>>(xn, wv, bv, nullptr, v, NTOK, EE_, EE_);
    // 3. fused flash attention (split score + online softmax + P@V)
    flash_k<<<dim3(LL_/128, NZ), blk, FSMEM>>>(q, k, v, ctx);
    // 4. O proj + residual
    gemm_k<1,0,2><<<gE, blk, SMG>>>(ctx, wo, bo, x, hidden, NTOK, EE_, EE_);
    // 5. LN2 + FFN
    ln_k<<<NTOK, blk>>>(hidden, ln2_w, ln2_b, hn);
    gemm_k<2,0,2><<<gF, blk, SMG>>>(hn, wu, bu, nullptr, up, NTOK, FF_, EE_);
    gemm_k<1,0,2><<<gE, blk, SMG>>>(up, wd, bd, hidden, out, NTOK, EE_, FF_);
    (void)in_sizes; (void)n_in; (void)out_size;
}

// round 16
// speedup vs baseline: 1.0588x; 1.0566x over previous
#include <cuda_runtime.h>
#include <cstdint>

#define BB_   2
#define LL_   2048
#define EE_   1024
#define HH_   16
#define DH_   64
#define FF_   4096
#define NTOK  (BB_*LL_)
#define NZ    (BB_*HH_)

// ---------------- scratch ----------------
__device__ float g_xn[NTOK*EE_];
__device__ float g_qh[NTOK*EE_];
__device__ float g_ql[NTOK*EE_];
__device__ float g_kh[NTOK*EE_];
__device__ float g_kl[NTOK*EE_];
__device__ float g_v [NTOK*EE_];
__device__ float g_ctx[NTOK*EE_];
__device__ float g_hidden[NTOK*EE_];
__device__ float g_hn[NTOK*EE_];
__device__ float g_up[(size_t)NTOK*FF_];

// ---------------- helpers ----------------
__device__ __forceinline__ uint32_t f2tf(float x){
    uint32_t r; asm("cvt.rna.tf32.f32 %0, %1;" : "=r"(r) : "f"(x)); return r;
}
__device__ __forceinline__ float rndf(float x){ return __uint_as_float(f2tf(x)); }
__device__ __forceinline__ void mma_tf32(float c[4], const uint32_t a[4], const uint32_t b[2]){
    asm volatile("mma.sync.aligned.m16n8k8.row.col.f32.tf32.tf32.f32 "
        "{%0,%1,%2,%3},{%4,%5,%6,%7},{%8,%9},{%0,%1,%2,%3};"
        : "+f"(c[0]), "+f"(c[1]), "+f"(c[2]), "+f"(c[3])
        : "r"(a[0]), "r"(a[1]), "r"(a[2]), "r"(a[3]), "r"(b[0]), "r"(b[1]));
}
__device__ __forceinline__ void cp16(void* dst, const void* src){
    uint32_t d = (uint32_t)__cvta_generic_to_shared(dst);
    asm volatile("cp.async.cg.shared.global [%0], [%1], 16;" :: "r"(d), "l"(src));
}
__device__ __forceinline__ void cp_commit(){ asm volatile("cp.async.commit_group;" ::: "memory"); }
template<int N> __device__ __forceinline__ void cp_wait(){
    asm volatile("cp.async.wait_group %0;" :: "n"(N) : "memory");
}

// ---------------- LayerNorm ----------------
__global__ void ln_k(const float* __restrict__ X, const float* __restrict__ w,
                     const float* __restrict__ bb, float* __restrict__ O)
{
    __shared__ float red[256];
    const int t = threadIdx.x;
    const size_t off = (size_t)blockIdx.x * EE_;
    float4 v = *(const float4*)(X + off + t*4);
    red[t] = v.x + v.y + v.z + v.w;
    __syncthreads();
    #pragma unroll
    for (int s = 128; s > 0; s >>= 1){ if (t < s) red[t] += red[t+s]; __syncthreads(); }
    float mu = red[0] * (1.f/1024.f);
    __syncthreads();
    float d0 = v.x-mu, d1 = v.y-mu, d2 = v.z-mu, d3 = v.w-mu;
    red[t] = d0*d0 + d1*d1 + d2*d2 + d3*d3;
    __syncthreads();
    #pragma unroll
    for (int s = 128; s > 0; s >>= 1){ if (t < s) red[t] += red[t+s]; __syncthreads(); }
    float inv = rsqrtf(red[0] * (1.f/1024.f) + 1e-5f);
    float4 wv = *(const float4*)(w + t*4);
    float4 bv = *(const float4*)(bb + t*4);
    float4 o;
    o.x = d0*inv*wv.x + bv.x;  o.y = d1*inv*wv.y + bv.y;
    o.z = d2*inv*wv.z + bv.z;  o.w = d3*inv*wv.w + bv.w;
    *(float4*)(O + off + t*4) = o;
}

// ---------------- tf32 GEMM: CTA 128x128, warp 64x32 ----------------
// EPI: 0 bias, 1 bias+res, 2 bias+gelu, 3 bias+round
// SPLIT: A-operand split (2 MMAs).  SOUT: write hi/lo pair (for Q/K).
#define GSS 8832   // 128*36 + 32*132

template<int EPI, int SPLIT, int MINB, bool SOUT>
__global__ void __launch_bounds__(256, MINB) gemm_k(
    const float* __restrict__ A, const float* __restrict__ W,
    const float* __restrict__ bias, const float* __restrict__ res,
    float* __restrict__ C, float* __restrict__ Clo, int M, int N, int K)
{
    extern __shared__ float sm[];
    const int tid  = threadIdx.x;
    const int bm   = blockIdx.y*128, bn = blockIdx.x*128;
    const int lane = tid & 31, warp = tid >> 5;
    const int wm   = warp >> 2, wn = warp & 3;
    const int gid  = lane >> 2, t4 = lane & 3;

    float acc[4][4][4];
    #pragma unroll
    for (int a=0;a<4;a++)
    #pragma unroll
    for (int b=0;b<4;b++)
    #pragma unroll
    for (int c=0;c<4;c++) acc[a][b][c] = 0.f;

    const int ar = tid >> 3, ac4 = tid & 7;
    const int br = tid >> 5, bc4 = tid & 31;
    const float* Ap = A + (size_t)(bm+ar)*K + ac4*4;
    const float* Wp = W + (size_t)br*N + bn + bc4*4;
    const int KT = K >> 5;

    auto issue = [&](int t){
        float* As = sm + (t&1)*GSS;
        float* Bs = As + 4608;
        const float* ap = Ap + t*32;
        const float* wp = Wp + (size_t)t*32*N;
        #pragma unroll
        for (int i=0;i<4;i++) cp16(As + (ar+32*i)*36 + ac4*4, ap + (size_t)(32*i)*K);
        #pragma unroll
        for (int i=0;i<4;i++) cp16(Bs + (br+8*i)*132 + bc4*4, wp + (size_t)(8*i)*N);
        cp_commit();
    };

    issue(0);
    for (int t = 0; t < KT; t++){
        if (t+1 < KT){ issue(t+1); cp_wait<1>(); }
        else         { cp_wait<0>(); }
        __syncthreads();
        const float* As = sm + (t&1)*GSS;
        const float* Bs = As + 4608;
        #pragma unroll
        for (int ks=0;ks<4;ks++){
            uint32_t ah[4][4], al[4][4], bh[4][2];
            #pragma unroll
            for (int mi=0;mi<4;mi++){
                const int r0 = (wm*64 + mi*16 + gid)*36 + ks*8 + t4;
                float x0 = As[r0], x1 = As[r0+8*36], x2 = As[r0+4], x3 = As[r0+8*36+4];
                ah[mi][0]=f2tf(x0); ah[mi][1]=f2tf(x1); ah[mi][2]=f2tf(x2); ah[mi][3]=f2tf(x3);
                if (SPLIT){
                    al[mi][0]=f2tf(x0-__uint_as_float(ah[mi][0]));
                    al[mi][1]=f2tf(x1-__uint_as_float(ah[mi][1]));
                    al[mi][2]=f2tf(x2-__uint_as_float(ah[mi][2]));
                    al[mi][3]=f2tf(x3-__uint_as_float(ah[mi][3]));
                }
            }
            #pragma unroll
            for (int ni=0;ni<4;ni++){
                const int c0 = wn*32 + ni*8 + gid;
                bh[ni][0]=f2tf(Bs[(ks*8+t4)*132 + c0]);
                bh[ni][1]=f2tf(Bs[(ks*8+t4+4)*132 + c0]);
            }
            #pragma unroll
            for (int mi=0;mi<4;mi++)
            #pragma unroll
            for (int ni=0;ni<4;ni++){
                mma_tf32(acc[mi][ni], ah[mi], bh[ni]);
                if (SPLIT) mma_tf32(acc[mi][ni], al[mi], bh[ni]);
            }
        }
        __syncthreads();
    }

    #pragma unroll
    for (int mi=0;mi<4;mi++)
    #pragma unroll
    for (int ni=0;ni<4;ni++){
        const int row0 = bm + wm*64 + mi*16 + gid;
        const int col0 = bn + wn*32 + ni*8 + t4*2;
        #pragma unroll
        for (int i=0;i<4;i++){
            const int row = row0 + ((i>=2)?8:0);
            const int col = col0 + (i&1);
            float v = acc[mi][ni][i] + bias[col];
            const size_t o = (size_t)row*N + col;
            if (SOUT){
                float h = rndf(v);
                C[o] = h; Clo[o] = rndf(v - h);
            } else if (EPI == 1){
                C[o] = v + res[o];
            } else if (EPI == 2){
                C[o] = 0.5f*v*(1.0f + erff(v*0.70710678118654752f));
            } else if (EPI == 3){
                C[o] = rndf(v);
            } else {
                C[o] = v;
            }
        }
    }
}

// ---------------- flash attention: ctx = softmax(8*QK^T) @ V ----------------
// Operands pre-split (Qh/Ql/Kh/Kl) and pre-rounded (V): zero CVT in S path.
// grid (LL/128, NZ), 8 warps; warp owns 16 q rows x all keys. Key tile = 64.
// smem (floats): Qh 2x128x36 @0 (9216) | Ql @9216 (9216)
//   stages @18432 + s*13824: Kh 2x64x36 (4608) | Kl (4608) | Vs 64x72 (4608)
//   Ps 128x68 @46080 (8704)  -> total 54784 floats = 219136 B
#define FQH   0
#define FQL   9216
#define FKV   18432
#define FSTG  13824
#define FPS   46080
#define FSMEM ((FPS + 8704)*4)

__global__ void __launch_bounds__(256, 1) flash_k(
    const float* __restrict__ Qh, const float* __restrict__ Ql,
    const float* __restrict__ Kh, const float* __restrict__ Kl,
    const float* __restrict__ V,  float* __restrict__ Ctx)
{
    extern __shared__ float sm[];
    const int tid = threadIdx.x, warp = tid >> 5, lane = tid & 31;
    const int gid = lane >> 2, t4 = lane & 3;
    const int z = blockIdx.y, b = z >> 4, h = z & 15;
    const int bm = blockIdx.x*128;
    float* Ps = sm + FPS;

    // ---- Q tiles (hi+lo): 128 rows x 64 d, two 36-stride chunks each ----
    {
        const int crow = tid >> 1, half = tid & 1;
        const size_t qo = ((size_t)(b*LL_ + bm + crow)*HH_ + h)*DH_ + half*32;
        #pragma unroll
        for (int i=0;i<8;i++){
            cp16(sm + FQH + half*4608 + crow*36 + i*4, Qh + qo + i*4);
            cp16(sm + FQL + half*4608 + crow*36 + i*4, Ql + qo + i*4);
        }
    }
    // ---- KV tile loader: 64 keys x 64 d (Kh, Kl, V) ----
    const int krow = tid >> 2, kq = tid & 3;
    auto issueKV = [&](int j){
        float* kh = sm + FKV + (j&1)*FSTG;
        float* kl = kh + 4608;
        float* vs = kh + 9216;
        const size_t ko = ((size_t)(b*LL_ + j*64 + krow)*HH_ + h)*DH_;
        #pragma unroll
        for (int i=0;i<4;i++){
            const int d = kq*16 + i*4;
            const int chunk = d >> 5, col = d & 31;
            cp16(kh + chunk*2304 + krow*36 + col, Kh + ko + d);
            cp16(kl + chunk*2304 + krow*36 + col, Kl + ko + d);
            cp16(vs + krow*72 + d,               V  + ko + d);
        }
        cp_commit();
    };
    issueKV(0);

    float m_s[2] = {-1e30f, -1e30f};
    float l_s[2] = {0.f, 0.f};
    float acc_o[8][4];
    #pragma unroll
    for (int n=0;n<8;n++)
    #pragma unroll
    for (int i=0;i<4;i++) acc_o[n][i] = 0.f;

    const uint32_t* uQh = (const uint32_t*)(sm + FQH);
    const uint32_t* uQl = (const uint32_t*)(sm + FQL);

    const int NT = LL_/64;   // 32
    for (int j = 0; j < NT; j++){
        if (j+1 < NT){ issueKV(j+1); cp_wait<1>(); }
        else         { cp_wait<0>(); }
        __syncthreads();
        const uint32_t* uKh = (const uint32_t*)(sm + FKV + (j&1)*FSTG);
        const uint32_t* uKl = uKh + 4608;
        const uint32_t* uVs = uKh + 9216;

        // ---- S tile 16x64 per warp: 3-MMA split, pure-LDS fragments ----
        float s_acc[8][4];
        #pragma unroll
        for (int n=0;n<8;n++)
        #pragma unroll
        for (int i=0;i<4;i++) s_acc[n][i] = 0.f;
        #pragma unroll
        for (int kt=0;kt<2;kt++)
        #pragma unroll
        for (int ks=0;ks<4;ks++){
            uint32_t ah[4], al[4];
            const int r0 = kt*4608 + (warp*16 + gid)*36 + ks*8 + t4;
            ah[0]=uQh[r0]; ah[1]=uQh[r0+8*36]; ah[2]=uQh[r0+4]; ah[3]=uQh[r0+8*36+4];
            al[0]=uQl[r0]; al[1]=uQl[r0+8*36]; al[2]=uQl[r0+4]; al[3]=uQl[r0+8*36+4];
            #pragma unroll
            for (int ni=0;ni<8;ni++){
                const int c = kt*2304 + (ni*8 + gid)*36 + ks*8 + t4;
                uint32_t bh[2] = { uKh[c], uKh[c+4] };
                uint32_t bl[2] = { uKl[c], uKl[c+4] };
                mma_tf32(s_acc[ni], ah, bh);
                mma_tf32(s_acc[ni], ah, bl);
                mma_tf32(s_acc[ni], al, bh);
            }
        }
        // ---- online softmax (rows warp*16+gid, +8; reduction over t4 lanes) ----
        float mx0 = -1e30f, mx1 = -1e30f;
        #pragma unroll
        for (int ni=0;ni<8;ni++){
            s_acc[ni][0]*=8.f; s_acc[ni][1]*=8.f; s_acc[ni][2]*=8.f; s_acc[ni][3]*=8.f;
            mx0 = fmaxf(mx0, fmaxf(s_acc[ni][0], s_acc[ni][1]));
            mx1 = fmaxf(mx1, fmaxf(s_acc[ni][2], s_acc[ni][3]));
        }
        mx0 = fmaxf(mx0, __shfl_xor_sync(0xFFFFFFFFu, mx0, 1));
        mx0 = fmaxf(mx0, __shfl_xor_sync(0xFFFFFFFFu, mx0, 2));
        mx1 = fmaxf(mx1, __shfl_xor_sync(0xFFFFFFFFu, mx1, 1));
        mx1 = fmaxf(mx1, __shfl_xor_sync(0xFFFFFFFFu, mx1, 2));
        const float mn0 = fmaxf(m_s[0], mx0), mn1 = fmaxf(m_s[1], mx1);
        const float a0 = expf(m_s[0]-mn0),  a1 = expf(m_s[1]-mn1);
        float sum0 = 0.f, sum1 = 0.f;
        #pragma unroll
        for (int ni=0;ni<8;ni++){
            float p0 = expf(s_acc[ni][0]-mn0), p1 = expf(s_acc[ni][1]-mn0);
            float p2 = expf(s_acc[ni][2]-mn1), p3 = expf(s_acc[ni][3]-mn1);
            sum0 += p0+p1; sum1 += p2+p3;
            const int cb = ni*8 + 2*t4;
            float2 v01 = {p0,p1}, v23 = {p2,p3};
            *(float2*)(Ps + (warp*16+gid)*68 + cb)   = v01;
            *(float2*)(Ps + (warp*16+gid+8)*68 + cb) = v23;
        }
        sum0 += __shfl_xor_sync(0xFFFFFFFFu, sum0, 1);
        sum0 += __shfl_xor_sync(0xFFFFFFFFu, sum0, 2);
        sum1 += __shfl_xor_sync(0xFFFFFFFFu, sum1, 1);
        sum1 += __shfl_xor_sync(0xFFFFFFFFu, sum1, 2);
        l_s[0] = l_s[0]*a0 + sum0;  l_s[1] = l_s[1]*a1 + sum1;
        m_s[0] = mn0;               m_s[1] = mn1;
        #pragma unroll
        for (int ni=0;ni<8;ni++){
            acc_o[ni][0]*=a0; acc_o[ni][1]*=a0; acc_o[ni][2]*=a1; acc_o[ni][3]*=a1;
        }
        __syncwarp();   // P is warp-local
        // ---- O += P @ V  (V pre-rounded: pure-LDS B-frags) ----
        #pragma unroll
        for (int k8=0;k8<8;k8++){
            uint32_t a[4];
            const int r = (warp*16 + gid)*68 + k8*8 + t4;
            a[0]=f2tf(Ps[r]);   a[1]=f2tf(Ps[r+8*68]);
            a[2]=f2tf(Ps[r+4]); a[3]=f2tf(Ps[r+8*68+4]);
            #pragma unroll
            for (int ni=0;ni<8;ni++){
                uint32_t bb[2];
                bb[0] = uVs[(k8*8+t4)*72 + ni*8 + gid];
                bb[1] = uVs[(k8*8+t4+4)*72 + ni*8 + gid];
                mma_tf32(acc_o[ni], a, bb);
            }
        }
        __syncthreads();   // protect KV buffer reuse next iteration
    }

    // ---- epilogue ----
    const float inv0 = 1.f/l_s[0], inv1 = 1.f/l_s[1];
    const int r0 = bm + warp*16 + gid, r1 = r0 + 8;
    float* c0p = Ctx + ((size_t)(b*LL_ + r0)*HH_ + h)*DH_;
    float* c1p = Ctx + ((size_t)(b*LL_ + r1)*HH_ + h)*DH_;
    #pragma unroll
    for (int ni=0;ni<8;ni++){
        const int cb = ni*8 + 2*t4;
        float2 o0 = { acc_o[ni][0]*inv0, acc_o[ni][1]*inv0 };
        float2 o1 = { acc_o[ni][2]*inv1, acc_o[ni][3]*inv1 };
        *(float2*)(c0p + cb) = o0;
        *(float2*)(c1p + cb) = o1;
    }
}

// ---------------- launch ----------------
extern "C" void kernel_launch(void* const* d_in, const int* in_sizes, int n_in,
                              void* d_out, int out_size)
{
    const float* x     = (const float*)d_in[0];
    const float* ln1_w = (const float*)d_in[1];
    const float* ln1_b = (const float*)d_in[2];
    const float* wq    = (const float*)d_in[3];
    const float* bq    = (const float*)d_in[4];
    const float* wk    = (const float*)d_in[5];
    const float* bk    = (const float*)d_in[6];
    const float* wv    = (const float*)d_in[7];
    const float* bv    = (const float*)d_in[8];
    const float* wo    = (const float*)d_in[9];
    const float* bo    = (const float*)d_in[10];
    const float* ln2_w = (const float*)d_in[11];
    const float* ln2_b = (const float*)d_in[12];
    const float* wu    = (const float*)d_in[13];
    const float* bu    = (const float*)d_in[14];
    const float* wd    = (const float*)d_in[15];
    const float* bd    = (const float*)d_in[16];
    float* out = (float*)d_out;

    float *xn,*qh,*ql,*kh,*kl,*v,*ctx,*hidden,*hn,*up;
    cudaGetSymbolAddress((void**)&xn,  g_xn);
    cudaGetSymbolAddress((void**)&qh,  g_qh);
    cudaGetSymbolAddress((void**)&ql,  g_ql);
    cudaGetSymbolAddress((void**)&kh,  g_kh);
    cudaGetSymbolAddress((void**)&kl,  g_kl);
    cudaGetSymbolAddress((void**)&v,   g_v);
    cudaGetSymbolAddress((void**)&ctx, g_ctx);
    cudaGetSymbolAddress((void**)&hidden, g_hidden);
    cudaGetSymbolAddress((void**)&hn,  g_hn);
    cudaGetSymbolAddress((void**)&up,  g_up);

    const int SMG = 2*GSS*4;   // 70656
    cudaFuncSetAttribute((gemm_k<0,1,1,true >), cudaFuncAttributeMaxDynamicSharedMemorySize, SMG);
    cudaFuncSetAttribute((gemm_k<3,0,2,false>), cudaFuncAttributeMaxDynamicSharedMemorySize, SMG);
    cudaFuncSetAttribute((gemm_k<1,0,2,false>), cudaFuncAttributeMaxDynamicSharedMemorySize, SMG);
    cudaFuncSetAttribute((gemm_k<2,0,2,false>), cudaFuncAttributeMaxDynamicSharedMemorySize, SMG);
    cudaFuncSetAttribute(flash_k,               cudaFuncAttributeMaxDynamicSharedMemorySize, FSMEM);

    const dim3 blk(256);
    const dim3 gE(EE_/128, NTOK/128);    // (8, 32)
    const dim3 gF(FF_/128, NTOK/128);    // (32, 32)

    // 1. LN1
    ln_k<<<NTOK, blk>>>(x, ln1_w, ln1_b, xn);
    // 2. Q, K (A-split 2-MMA, hi/lo out), V (single, tf32-rounded out)
    gemm_k<0,1,1,true ><<<gE, blk, SMG>>>(xn, wq, bq, nullptr, qh, ql, NTOK, EE_, EE_);
    gemm_k<0,1,1,true ><<<gE, blk, SMG>>>(xn, wk, bk, nullptr, kh, kl, NTOK, EE_, EE_);
    gemm_k<3,0,2,false><<<gE, blk, SMG>>>(xn, wv, bv, nullptr, v, nullptr, NTOK, EE_, EE_);
    // 3. fused flash attention (pre-split operands, pure-LDS fragments)
    flash_k<<<dim3(LL_/128, NZ), blk, FSMEM>>>(qh, ql, kh, kl, v, ctx);
    // 4. O proj + residual
    gemm_k<1,0,2,false><<<gE, blk, SMG>>>(ctx, wo, bo, x, hidden, nullptr, NTOK, EE_, EE_);
    // 5. LN2 + FFN
    ln_k<<<NTOK, blk>>>(hidden, ln2_w, ln2_b, hn);
    gemm_k<2,0,2,false><<<gF, blk, SMG>>>(hn, wu, bu, nullptr, up, nullptr, NTOK, FF_, EE_);
    gemm_k<1,0,2,false><<<gE, blk, SMG>>>(up, wd, bd, hidden, out, nullptr, NTOK, EE_, FF_);
    (void)in_sizes; (void)n_in; (void)out_size;
}